// round 10
// baseline (speedup 1.0000x reference)
#include <cuda_runtime.h>
#include <cuda_bf16.h>
#include <cstdint>

// fid[p] = clip( (va.vb)^2 / (|va|^2 |vb|^2), 0, 1 )
// va = tanh( relu(xa @ W1 + b1) @ W2 + b2 )   (quantum circuit is unitary -> cancels)
//
// Warp-specialized: 8 consumer warps (mma.sync m16n8k16 bf16 split hi/lo, 32x32 tiles,
// M=128/block) + 2 producer warps (A convert/stage, B cp.async from pre-converted W1),
// 3-stage mbarrier pipeline. 1024 blocks.

#define KDIM   784
#define KC     16
#define NCHUNK 49
#define NSTAGE 3
#define ASTR   24      // uint16 per smem row (48 B): conflict-free frags
#define HSTR   66

// dynamic smem byte offsets
#define OFF_AHI(s) ((s) * 6144)              // 128 rows * 48 B
#define OFF_ALO(s) (18432 + (s) * 6144)
#define OFF_BHI(s) (36864 + (s) * 3072)      // 64 rows * 48 B
#define OFF_BLO(s) (46080 + (s) * 3072)
#define OFF_W2   55296
#define OFF_B1   59392
#define OFF_B2   59648
#define OFF_MB   59712                        // full[s] at +16s, empty[s] at +16s+8
#define SMEM_BYTES 59776
// epilogue overlay (inside stage region, used after mainloop)
#define OFF_H    0                            // 128*66*4 = 33792
#define OFF_VS   36864                        // 128*16*4 = 8192
#define OFF_SSQ  45056                        // 128*4

__device__ uint16_t g_W1T_hi[64 * KDIM];   // K-major: [n][k]
__device__ uint16_t g_W1T_lo[64 * KDIM];

#define MMA(d, a, b) asm volatile( \
    "mma.sync.aligned.m16n8k16.row.col.f32.bf16.bf16.f32 " \
    "{%0,%1,%2,%3}, {%4,%5,%6,%7}, {%8,%9}, {%0,%1,%2,%3};" \
    : "+f"(d[0]), "+f"(d[1]), "+f"(d[2]), "+f"(d[3]) \
    : "r"(a[0]), "r"(a[1]), "r"(a[2]), "r"(a[3]), "r"(b[0]), "r"(b[1]))

__device__ __forceinline__ uint32_t bf2u(__nv_bfloat162 v) { return *(uint32_t*)&v; }

__device__ __forceinline__ uint32_t hi2(float x, float y, uint32_t& lo) {
    __nv_bfloat162 h = __float22bfloat162_rn(make_float2(x, y));
    __nv_bfloat162 l = __float22bfloat162_rn(make_float2(
        x - __bfloat162float(h.x), y - __bfloat162float(h.y)));
    lo = bf2u(l);
    return bf2u(h);
}

// convert float4 -> 4x(hi,lo) bf16, store 8B hi + 8B lo
__device__ __forceinline__ void cvst4(float4 v, uint16_t* hi, uint16_t* lo) {
    uint2 h, l;
    h.x = hi2(v.x, v.y, l.x);
    h.y = hi2(v.z, v.w, l.y);
    *(uint2*)hi = h;
    *(uint2*)lo = l;
}

__device__ __forceinline__ void cp16(uint32_t dst, const void* src) {
    asm volatile("cp.async.ca.shared.global [%0], [%1], 16;" :: "r"(dst), "l"(src));
}
__device__ __forceinline__ void mbar_init(uint32_t a, uint32_t c) {
    asm volatile("mbarrier.init.shared.b64 [%0], %1;" :: "r"(a), "r"(c) : "memory");
}
__device__ __forceinline__ void mbar_arrive(uint32_t a) {
    asm volatile("{ .reg .b64 _t; mbarrier.arrive.shared.b64 _t, [%0]; }" :: "r"(a) : "memory");
}
__device__ __forceinline__ void cp_async_mbar_arrive(uint32_t a) {
    asm volatile("cp.async.mbarrier.arrive.noinc.shared.b64 [%0];" :: "r"(a) : "memory");
}
__device__ __forceinline__ void mbar_wait(uint32_t a, uint32_t par) {
    asm volatile(
        "{\n\t.reg .pred P;\n"
        "LW%=:\n\tmbarrier.try_wait.parity.shared.b64 P, [%0], %1;\n\t"
        "@P bra LD%=;\n\tbra LW%=;\n"
        "LD%=:\n\t}"
        :: "r"(a), "r"(par) : "memory");
}

__global__ void prep_w1(const float* __restrict__ W1) {
    int i = blockIdx.x * 256 + threadIdx.x;        // 12544 = 64 * 196
    int n  = i / 196;
    int k4 = (i - n * 196) * 4;
    uint32_t h0, h1, l0, l1;
    {
        float v0 = W1[(size_t)(k4 + 0) * 64 + n];
        float v1 = W1[(size_t)(k4 + 1) * 64 + n];
        float v2 = W1[(size_t)(k4 + 2) * 64 + n];
        float v3 = W1[(size_t)(k4 + 3) * 64 + n];
        h0 = hi2(v0, v1, l0);
        h1 = hi2(v2, v3, l1);
    }
    *(uint2*)&g_W1T_hi[n * KDIM + k4] = make_uint2(h0, h1);
    *(uint2*)&g_W1T_lo[n * KDIM + k4] = make_uint2(l0, l1);
}

__global__ __launch_bounds__(320)
void qcm_ws(const float* __restrict__ img_a,
            const float* __restrict__ img_b,
            const float* __restrict__ b1,
            const float* __restrict__ W2,
            const float* __restrict__ b2,
            float* __restrict__ out)
{
    extern __shared__ char smem[];
    const uint32_t sb = (uint32_t)__cvta_generic_to_shared(smem);
    float* W2s = (float*)(smem + OFF_W2);
    float* b1s = (float*)(smem + OFF_B1);
    float* b2s = (float*)(smem + OFF_B2);

    const int t  = threadIdx.x;
    const int p0 = blockIdx.x * 64;   // 64 pairs per block (128 rows)

    if (t == 0) {
        #pragma unroll
        for (int s = 0; s < NSTAGE; ++s) {
            mbar_init(sb + OFF_MB + 16 * s,     128);  // full: 64 STS-arrive + 64 cp-arrive
            mbar_init(sb + OFF_MB + 16 * s + 8, 256);  // empty: 256 consumer threads
        }
    }
    if (t < 256) {
        if (t < 64) b1s[t] = b1[t];
        if (t < 16) b2s[t] = b2[t];
        #pragma unroll
        for (int i = 0; i < 4; ++i) W2s[t + i * 256] = W2[t + i * 256];
    }
    __syncthreads();

    if (t >= 256) {
        // ================= PRODUCER (warps 8,9: 64 threads) =================
        const int pt   = t - 256;
        const int r0   = pt >> 1;          // 0..31
        const int half = pt & 1;           // k-half within chunk (8 floats)
        const float* rowp[4];
        int rowi[4];
        rowp[0] = img_a + (size_t)(p0 + r0)      * KDIM;  rowi[0] = r0;
        rowp[1] = img_a + (size_t)(p0 + r0 + 32) * KDIM;  rowi[1] = r0 + 32;
        rowp[2] = img_b + (size_t)(p0 + r0)      * KDIM;  rowi[2] = r0 + 64;
        rowp[3] = img_b + (size_t)(p0 + r0 + 32) * KDIM;  rowi[3] = r0 + 96;

        // B cp.async tasks: i 0,1 -> hi rows r0 / r0+32 ; i 2,3 -> lo rows r0 / r0+32
        const uint16_t* bsrc0 = g_W1T_hi + r0 * KDIM + half * 8;
        const uint16_t* bsrc1 = g_W1T_hi + (r0 + 32) * KDIM + half * 8;
        const uint16_t* bsrc2 = g_W1T_lo + r0 * KDIM + half * 8;
        const uint16_t* bsrc3 = g_W1T_lo + (r0 + 32) * KDIM + half * 8;
        const uint32_t bo0 = (uint32_t)(r0 * 48 + half * 16);
        const uint32_t bo1 = (uint32_t)((r0 + 32) * 48 + half * 16);

        float4 buf[2][8];
        #pragma unroll
        for (int i = 0; i < 4; ++i) {            // prologue: chunk 0 -> regs
            buf[0][2 * i]     = *(const float4*)(rowp[i] + half * 8);
            buf[0][2 * i + 1] = *(const float4*)(rowp[i] + half * 8 + 4);
        }

        int s = 0, ph = 1;                        // first empty-waits pass immediately
        #pragma unroll 2
        for (int c = 0; c < NCHUNK; ++c) {
            const int cb = c & 1;
            mbar_wait(sb + OFF_MB + 16 * s + 8, ph);
            if (c + 1 < NCHUNK) {                 // prefetch next chunk's A
                const int k1 = (c + 1) * KC;
                #pragma unroll
                for (int i = 0; i < 4; ++i) {
                    buf[cb ^ 1][2 * i]     = *(const float4*)(rowp[i] + k1 + half * 8);
                    buf[cb ^ 1][2 * i + 1] = *(const float4*)(rowp[i] + k1 + half * 8 + 4);
                }
            }
            const int k0 = c * KC;
            cp16(sb + OFF_BHI(s) + bo0, bsrc0 + k0);
            cp16(sb + OFF_BHI(s) + bo1, bsrc1 + k0);
            cp16(sb + OFF_BLO(s) + bo0, bsrc2 + k0);
            cp16(sb + OFF_BLO(s) + bo1, bsrc3 + k0);

            char* ahi = smem + OFF_AHI(s);
            char* alo = smem + OFF_ALO(s);
            #pragma unroll
            for (int i = 0; i < 4; ++i) {
                int d = rowi[i] * 48 + half * 16;
                cvst4(buf[cb][2 * i],     (uint16_t*)(ahi + d),     (uint16_t*)(alo + d));
                cvst4(buf[cb][2 * i + 1], (uint16_t*)(ahi + d + 8), (uint16_t*)(alo + d + 8));
            }
            mbar_arrive(sb + OFF_MB + 16 * s);          // STS visible (release)
            cp_async_mbar_arrive(sb + OFF_MB + 16 * s); // arrives when cp.asyncs land
            if (++s == NSTAGE) { s = 0; ph ^= 1; }
        }
        // producers done; consumers handle epilogue with named barriers
    } else {
        // ================= CONSUMER (warps 0-7: 256 threads) =================
        const int lane = t & 31;
        const int wid  = t >> 5;
        const int wr   = wid >> 1;
        const int wc   = wid & 1;
        const int g    = lane >> 2;
        const int tig  = lane & 3;

        float acc[2][4][4];
        #pragma unroll
        for (int mt = 0; mt < 2; ++mt)
            #pragma unroll
            for (int nt = 0; nt < 4; ++nt)
                #pragma unroll
                for (int j = 0; j < 4; ++j) acc[mt][nt][j] = 0.f;

        int s = 0, ph = 0;
        for (int c = 0; c < NCHUNK; ++c) {
            mbar_wait(sb + OFF_MB + 16 * s, ph);
            const uint16_t* Ah = (const uint16_t*)(smem + OFF_AHI(s));
            const uint16_t* Al = (const uint16_t*)(smem + OFF_ALO(s));
            const uint16_t* Bh = (const uint16_t*)(smem + OFF_BHI(s));
            const uint16_t* Bl = (const uint16_t*)(smem + OFF_BLO(s));

            uint32_t bh[4][2], bl[4][2];
            #pragma unroll
            for (int nt = 0; nt < 4; ++nt) {
                int bb = (wc * 32 + nt * 8 + g) * ASTR + 2 * tig;
                bh[nt][0] = *(const uint32_t*)&Bh[bb];
                bh[nt][1] = *(const uint32_t*)&Bh[bb + 8];
                bl[nt][0] = *(const uint32_t*)&Bl[bb];
                bl[nt][1] = *(const uint32_t*)&Bl[bb + 8];
            }
            uint32_t ah[2][4], al[2][4];
            #pragma unroll
            for (int mt = 0; mt < 2; ++mt) {
                int fr = (wr * 32 + mt * 16 + g) * ASTR + 2 * tig;
                ah[mt][0] = *(const uint32_t*)&Ah[fr];
                ah[mt][1] = *(const uint32_t*)&Ah[fr + 8 * ASTR];
                ah[mt][2] = *(const uint32_t*)&Ah[fr + 8];
                ah[mt][3] = *(const uint32_t*)&Ah[fr + 8 * ASTR + 8];
                al[mt][0] = *(const uint32_t*)&Al[fr];
                al[mt][1] = *(const uint32_t*)&Al[fr + 8 * ASTR];
                al[mt][2] = *(const uint32_t*)&Al[fr + 8];
                al[mt][3] = *(const uint32_t*)&Al[fr + 8 * ASTR + 8];
            }
            mbar_arrive(sb + OFF_MB + 16 * s + 8);   // stage consumed (frags in regs)

            #pragma unroll
            for (int mt = 0; mt < 2; ++mt)
                #pragma unroll
                for (int nt = 0; nt < 4; ++nt) {
                    MMA(acc[mt][nt], ah[mt], bh[nt]);
                    MMA(acc[mt][nt], ah[mt], bl[nt]);
                    MMA(acc[mt][nt], al[mt], bh[nt]);
                }
            if (++s == NSTAGE) { s = 0; ph ^= 1; }
        }

        // ---- epilogue (consumer threads only; named barrier id 1, 256 threads) ----
        asm volatile("bar.sync 1, 256;" ::: "memory");   // all stage reads done

        float* Hs  = (float*)(smem + OFF_H);
        float* Vs  = (float*)(smem + OFF_VS);
        float* SSQ = (float*)(smem + OFF_SSQ);

        #pragma unroll
        for (int mt = 0; mt < 2; ++mt) {
            #pragma unroll
            for (int nt = 0; nt < 4; ++nt) {
                int row = wr * 32 + mt * 16 + g;
                int col = wc * 32 + nt * 8 + 2 * tig;
                float bx = b1s[col], by = b1s[col + 1];
                *(float2*)&Hs[row * HSTR + col] =
                    make_float2(fmaxf(acc[mt][nt][0] + bx, 0.f), fmaxf(acc[mt][nt][1] + by, 0.f));
                *(float2*)&Hs[(row + 8) * HSTR + col] =
                    make_float2(fmaxf(acc[mt][nt][2] + bx, 0.f), fmaxf(acc[mt][nt][3] + by, 0.f));
            }
        }
        asm volatile("bar.sync 1, 256;" ::: "memory");

        {   // v = tanh(H @ W2 + b2): 2 threads per row, 8 outs each
            int row  = t >> 1;
            int half = t & 1;
            float sv[8];
            float4 bb0 = *(const float4*)&b2s[half * 8];
            float4 bb1 = *(const float4*)&b2s[half * 8 + 4];
            sv[0]=bb0.x; sv[1]=bb0.y; sv[2]=bb0.z; sv[3]=bb0.w;
            sv[4]=bb1.x; sv[5]=bb1.y; sv[6]=bb1.z; sv[7]=bb1.w;
            #pragma unroll 8
            for (int kk = 0; kk < 64; ++kk) {
                float h = Hs[row * HSTR + kk];
                float4 w0 = *(const float4*)&W2s[kk * 16 + half * 8];
                float4 w1 = *(const float4*)&W2s[kk * 16 + half * 8 + 4];
                sv[0]+=h*w0.x; sv[1]+=h*w0.y; sv[2]+=h*w0.z; sv[3]+=h*w0.w;
                sv[4]+=h*w1.x; sv[5]+=h*w1.y; sv[6]+=h*w1.z; sv[7]+=h*w1.w;
            }
            float sq = 0.f;
            #pragma unroll
            for (int j = 0; j < 8; ++j) { sv[j] = tanhf(sv[j]); sq += sv[j] * sv[j]; }
            sq += __shfl_xor_sync(0xffffffffu, sq, 1);
            *(float4*)&Vs[row * 16 + half * 8]     = make_float4(sv[0], sv[1], sv[2], sv[3]);
            *(float4*)&Vs[row * 16 + half * 8 + 4] = make_float4(sv[4], sv[5], sv[6], sv[7]);
            if (half == 0) SSQ[row] = sq;
        }
        asm volatile("bar.sync 1, 256;" ::: "memory");

        if (t < 64) {
            float d = 0.f;
            #pragma unroll
            for (int j4 = 0; j4 < 4; ++j4) {
                float4 a = *(const float4*)&Vs[t * 16 + j4 * 4];
                float4 b = *(const float4*)&Vs[(t + 64) * 16 + j4 * 4];
                d += a.x * b.x + a.y * b.y + a.z * b.z + a.w * b.w;
            }
            float fid = (d * d) / (SSQ[t] * SSQ[t + 64]);
            out[p0 + t] = fminf(fmaxf(fid, 0.f), 1.f);
        }
    }
}

extern "C" void kernel_launch(void* const* d_in, const int* in_sizes, int n_in,
                              void* d_out, int out_size)
{
    const float* img_a = (const float*)d_in[0];
    const float* img_b = (const float*)d_in[1];
    const float* W1    = (const float*)d_in[2];
    const float* b1    = (const float*)d_in[3];
    const float* W2    = (const float*)d_in[4];
    const float* b2    = (const float*)d_in[5];
    // d_in[6] = theta: unused — the circuit is unitary, fidelity is invariant.
    float* out = (float*)d_out;

    cudaFuncSetAttribute(qcm_ws, cudaFuncAttributeMaxDynamicSharedMemorySize, SMEM_BYTES);
    prep_w1<<<49, 256>>>(W1);                   // W1 -> K-major bf16 hi/lo
    int blocks = out_size / 64;                 // 1024
    qcm_ws<<<blocks, 320, SMEM_BYTES>>>(img_a, img_b, b1, W2, b2, out);
}

// round 11
// speedup vs baseline: 1.0027x; 1.0027x over previous
#include <cuda_runtime.h>
#include <cuda_bf16.h>
#include <cstdint>

// fid[p] = clip( (va.vb)^2 / (|va|^2 |vb|^2), 0, 1 )
// va = tanh( relu(xa @ W1 + b1) @ W2 + b2 )   (quantum circuit is unitary -> cancels)
//
// Warp-specialized: 8 consumer warps (mma.sync m16n8k16 bf16 split hi/lo, 32x32 tiles,
// M=128/block) + 2 producer warps (A convert/stage, B cp.async from pre-converted W1),
// 3-stage mbarrier pipeline. 1024 blocks.

#define KDIM   784
#define KC     16
#define NCHUNK 49
#define NSTAGE 3
#define ASTR   24      // uint16 per smem row (48 B): conflict-free frags
#define HSTR   66

// dynamic smem byte offsets
#define OFF_AHI(s) ((s) * 6144)              // 128 rows * 48 B
#define OFF_ALO(s) (18432 + (s) * 6144)
#define OFF_BHI(s) (36864 + (s) * 3072)      // 64 rows * 48 B
#define OFF_BLO(s) (46080 + (s) * 3072)
#define OFF_W2   55296
#define OFF_B1   59392
#define OFF_B2   59648
#define OFF_MB   59712                        // full[s] at +16s, empty[s] at +16s+8
#define SMEM_BYTES 59776
// epilogue overlay (inside stage region, used after mainloop)
#define OFF_H    0                            // 128*66*4 = 33792
#define OFF_VS   36864                        // 128*16*4 = 8192
#define OFF_SSQ  45056                        // 128*4

__device__ uint16_t g_W1T_hi[64 * KDIM];   // K-major: [n][k]
__device__ uint16_t g_W1T_lo[64 * KDIM];

#define MMA(d, a, b) asm volatile( \
    "mma.sync.aligned.m16n8k16.row.col.f32.bf16.bf16.f32 " \
    "{%0,%1,%2,%3}, {%4,%5,%6,%7}, {%8,%9}, {%0,%1,%2,%3};" \
    : "+f"(d[0]), "+f"(d[1]), "+f"(d[2]), "+f"(d[3]) \
    : "r"(a[0]), "r"(a[1]), "r"(a[2]), "r"(a[3]), "r"(b[0]), "r"(b[1]))

__device__ __forceinline__ uint32_t bf2u(__nv_bfloat162 v) { return *(uint32_t*)&v; }

__device__ __forceinline__ uint32_t hi2(float x, float y, uint32_t& lo) {
    __nv_bfloat162 h = __float22bfloat162_rn(make_float2(x, y));
    __nv_bfloat162 l = __float22bfloat162_rn(make_float2(
        x - __bfloat162float(h.x), y - __bfloat162float(h.y)));
    lo = bf2u(l);
    return bf2u(h);
}

// convert float4 -> 4x(hi,lo) bf16, store 8B hi + 8B lo
__device__ __forceinline__ void cvst4(float4 v, uint16_t* hi, uint16_t* lo) {
    uint2 h, l;
    h.x = hi2(v.x, v.y, l.x);
    h.y = hi2(v.z, v.w, l.y);
    *(uint2*)hi = h;
    *(uint2*)lo = l;
}

__device__ __forceinline__ void cp16(uint32_t dst, const void* src) {
    asm volatile("cp.async.ca.shared.global [%0], [%1], 16;" :: "r"(dst), "l"(src));
}
__device__ __forceinline__ void mbar_init(uint32_t a, uint32_t c) {
    asm volatile("mbarrier.init.shared.b64 [%0], %1;" :: "r"(a), "r"(c) : "memory");
}
__device__ __forceinline__ void mbar_arrive(uint32_t a) {
    asm volatile("{ .reg .b64 _t; mbarrier.arrive.shared.b64 _t, [%0]; }" :: "r"(a) : "memory");
}
__device__ __forceinline__ void cp_async_mbar_arrive(uint32_t a) {
    asm volatile("cp.async.mbarrier.arrive.noinc.shared.b64 [%0];" :: "r"(a) : "memory");
}
__device__ __forceinline__ void mbar_wait(uint32_t a, uint32_t par) {
    asm volatile(
        "{\n\t.reg .pred P;\n"
        "LW%=:\n\tmbarrier.try_wait.parity.shared.b64 P, [%0], %1;\n\t"
        "@P bra LD%=;\n\tbra LW%=;\n"
        "LD%=:\n\t}"
        :: "r"(a), "r"(par) : "memory");
}

__global__ void prep_w1(const float* __restrict__ W1) {
    int i = blockIdx.x * 256 + threadIdx.x;        // 12544 = 64 * 196
    int n  = i / 196;
    int k4 = (i - n * 196) * 4;
    uint32_t h0, h1, l0, l1;
    {
        float v0 = W1[(size_t)(k4 + 0) * 64 + n];
        float v1 = W1[(size_t)(k4 + 1) * 64 + n];
        float v2 = W1[(size_t)(k4 + 2) * 64 + n];
        float v3 = W1[(size_t)(k4 + 3) * 64 + n];
        h0 = hi2(v0, v1, l0);
        h1 = hi2(v2, v3, l1);
    }
    *(uint2*)&g_W1T_hi[n * KDIM + k4] = make_uint2(h0, h1);
    *(uint2*)&g_W1T_lo[n * KDIM + k4] = make_uint2(l0, l1);
}

__global__ __launch_bounds__(320)
void qcm_ws(const float* __restrict__ img_a,
            const float* __restrict__ img_b,
            const float* __restrict__ b1,
            const float* __restrict__ W2,
            const float* __restrict__ b2,
            float* __restrict__ out)
{
    extern __shared__ char smem[];
    const uint32_t sb = (uint32_t)__cvta_generic_to_shared(smem);
    float* W2s = (float*)(smem + OFF_W2);
    float* b1s = (float*)(smem + OFF_B1);
    float* b2s = (float*)(smem + OFF_B2);

    const int t  = threadIdx.x;
    const int p0 = blockIdx.x * 64;   // 64 pairs per block (128 rows)

    if (t == 0) {
        #pragma unroll
        for (int s = 0; s < NSTAGE; ++s) {
            mbar_init(sb + OFF_MB + 16 * s,     128);  // full: 64 STS-arrive + 64 cp-arrive
            mbar_init(sb + OFF_MB + 16 * s + 8, 256);  // empty: 256 consumer threads
        }
    }
    if (t < 256) {
        if (t < 64) b1s[t] = b1[t];
        if (t < 16) b2s[t] = b2[t];
        #pragma unroll
        for (int i = 0; i < 4; ++i) W2s[t + i * 256] = W2[t + i * 256];
    }
    __syncthreads();

    if (t >= 256) {
        // ================= PRODUCER (warps 8,9: 64 threads) =================
        const int pt   = t - 256;
        const int r0   = pt >> 1;          // 0..31
        const int half = pt & 1;           // k-half within chunk (8 floats)
        const float* rowp[4];
        int rowi[4];
        rowp[0] = img_a + (size_t)(p0 + r0)      * KDIM;  rowi[0] = r0;
        rowp[1] = img_a + (size_t)(p0 + r0 + 32) * KDIM;  rowi[1] = r0 + 32;
        rowp[2] = img_b + (size_t)(p0 + r0)      * KDIM;  rowi[2] = r0 + 64;
        rowp[3] = img_b + (size_t)(p0 + r0 + 32) * KDIM;  rowi[3] = r0 + 96;

        // B cp.async tasks: i 0,1 -> hi rows r0 / r0+32 ; i 2,3 -> lo rows r0 / r0+32
        const uint16_t* bsrc0 = g_W1T_hi + r0 * KDIM + half * 8;
        const uint16_t* bsrc1 = g_W1T_hi + (r0 + 32) * KDIM + half * 8;
        const uint16_t* bsrc2 = g_W1T_lo + r0 * KDIM + half * 8;
        const uint16_t* bsrc3 = g_W1T_lo + (r0 + 32) * KDIM + half * 8;
        const uint32_t bo0 = (uint32_t)(r0 * 48 + half * 16);
        const uint32_t bo1 = (uint32_t)((r0 + 32) * 48 + half * 16);

        float4 buf[2][8];
        #pragma unroll
        for (int i = 0; i < 4; ++i) {            // prologue: chunk 0 -> regs
            buf[0][2 * i]     = *(const float4*)(rowp[i] + half * 8);
            buf[0][2 * i + 1] = *(const float4*)(rowp[i] + half * 8 + 4);
        }

        int s = 0, ph = 1;                        // first empty-waits pass immediately
        #pragma unroll 2
        for (int c = 0; c < NCHUNK; ++c) {
            const int cb = c & 1;
            mbar_wait(sb + OFF_MB + 16 * s + 8, ph);
            if (c + 1 < NCHUNK) {                 // prefetch next chunk's A
                const int k1 = (c + 1) * KC;
                #pragma unroll
                for (int i = 0; i < 4; ++i) {
                    buf[cb ^ 1][2 * i]     = *(const float4*)(rowp[i] + k1 + half * 8);
                    buf[cb ^ 1][2 * i + 1] = *(const float4*)(rowp[i] + k1 + half * 8 + 4);
                }
            }
            const int k0 = c * KC;
            cp16(sb + OFF_BHI(s) + bo0, bsrc0 + k0);
            cp16(sb + OFF_BHI(s) + bo1, bsrc1 + k0);
            cp16(sb + OFF_BLO(s) + bo0, bsrc2 + k0);
            cp16(sb + OFF_BLO(s) + bo1, bsrc3 + k0);

            char* ahi = smem + OFF_AHI(s);
            char* alo = smem + OFF_ALO(s);
            #pragma unroll
            for (int i = 0; i < 4; ++i) {
                int d = rowi[i] * 48 + half * 16;
                cvst4(buf[cb][2 * i],     (uint16_t*)(ahi + d),     (uint16_t*)(alo + d));
                cvst4(buf[cb][2 * i + 1], (uint16_t*)(ahi + d + 8), (uint16_t*)(alo + d + 8));
            }
            mbar_arrive(sb + OFF_MB + 16 * s);          // STS visible (release)
            cp_async_mbar_arrive(sb + OFF_MB + 16 * s); // arrives when cp.asyncs land
            if (++s == NSTAGE) { s = 0; ph ^= 1; }
        }
        // producers done; consumers handle epilogue with named barriers
    } else {
        // ================= CONSUMER (warps 0-7: 256 threads) =================
        const int lane = t & 31;
        const int wid  = t >> 5;
        const int wr   = wid >> 1;
        const int wc   = wid & 1;
        const int g    = lane >> 2;
        const int tig  = lane & 3;

        float acc[2][4][4];
        #pragma unroll
        for (int mt = 0; mt < 2; ++mt)
            #pragma unroll
            for (int nt = 0; nt < 4; ++nt)
                #pragma unroll
                for (int j = 0; j < 4; ++j) acc[mt][nt][j] = 0.f;

        int s = 0, ph = 0;
        for (int c = 0; c < NCHUNK; ++c) {
            mbar_wait(sb + OFF_MB + 16 * s, ph);
            const uint16_t* Ah = (const uint16_t*)(smem + OFF_AHI(s));
            const uint16_t* Al = (const uint16_t*)(smem + OFF_ALO(s));
            const uint16_t* Bh = (const uint16_t*)(smem + OFF_BHI(s));
            const uint16_t* Bl = (const uint16_t*)(smem + OFF_BLO(s));

            uint32_t bh[4][2], bl[4][2];
            #pragma unroll
            for (int nt = 0; nt < 4; ++nt) {
                int bb = (wc * 32 + nt * 8 + g) * ASTR + 2 * tig;
                bh[nt][0] = *(const uint32_t*)&Bh[bb];
                bh[nt][1] = *(const uint32_t*)&Bh[bb + 8];
                bl[nt][0] = *(const uint32_t*)&Bl[bb];
                bl[nt][1] = *(const uint32_t*)&Bl[bb + 8];
            }
            uint32_t ah[2][4], al[2][4];
            #pragma unroll
            for (int mt = 0; mt < 2; ++mt) {
                int fr = (wr * 32 + mt * 16 + g) * ASTR + 2 * tig;
                ah[mt][0] = *(const uint32_t*)&Ah[fr];
                ah[mt][1] = *(const uint32_t*)&Ah[fr + 8 * ASTR];
                ah[mt][2] = *(const uint32_t*)&Ah[fr + 8];
                ah[mt][3] = *(const uint32_t*)&Ah[fr + 8 * ASTR + 8];
                al[mt][0] = *(const uint32_t*)&Al[fr];
                al[mt][1] = *(const uint32_t*)&Al[fr + 8 * ASTR];
                al[mt][2] = *(const uint32_t*)&Al[fr + 8];
                al[mt][3] = *(const uint32_t*)&Al[fr + 8 * ASTR + 8];
            }
            mbar_arrive(sb + OFF_MB + 16 * s + 8);   // stage consumed (frags in regs)

            #pragma unroll
            for (int mt = 0; mt < 2; ++mt)
                #pragma unroll
                for (int nt = 0; nt < 4; ++nt) {
                    MMA(acc[mt][nt], ah[mt], bh[nt]);
                    MMA(acc[mt][nt], ah[mt], bl[nt]);
                    MMA(acc[mt][nt], al[mt], bh[nt]);
                }
            if (++s == NSTAGE) { s = 0; ph ^= 1; }
        }

        // ---- epilogue (consumer threads only; named barrier id 1, 256 threads) ----
        asm volatile("bar.sync 1, 256;" ::: "memory");   // all stage reads done

        float* Hs  = (float*)(smem + OFF_H);
        float* Vs  = (float*)(smem + OFF_VS);
        float* SSQ = (float*)(smem + OFF_SSQ);

        #pragma unroll
        for (int mt = 0; mt < 2; ++mt) {
            #pragma unroll
            for (int nt = 0; nt < 4; ++nt) {
                int row = wr * 32 + mt * 16 + g;
                int col = wc * 32 + nt * 8 + 2 * tig;
                float bx = b1s[col], by = b1s[col + 1];
                *(float2*)&Hs[row * HSTR + col] =
                    make_float2(fmaxf(acc[mt][nt][0] + bx, 0.f), fmaxf(acc[mt][nt][1] + by, 0.f));
                *(float2*)&Hs[(row + 8) * HSTR + col] =
                    make_float2(fmaxf(acc[mt][nt][2] + bx, 0.f), fmaxf(acc[mt][nt][3] + by, 0.f));
            }
        }
        asm volatile("bar.sync 1, 256;" ::: "memory");

        {   // v = tanh(H @ W2 + b2): 2 threads per row, 8 outs each
            int row  = t >> 1;
            int half = t & 1;
            float sv[8];
            float4 bb0 = *(const float4*)&b2s[half * 8];
            float4 bb1 = *(const float4*)&b2s[half * 8 + 4];
            sv[0]=bb0.x; sv[1]=bb0.y; sv[2]=bb0.z; sv[3]=bb0.w;
            sv[4]=bb1.x; sv[5]=bb1.y; sv[6]=bb1.z; sv[7]=bb1.w;
            #pragma unroll 8
            for (int kk = 0; kk < 64; ++kk) {
                float h = Hs[row * HSTR + kk];
                float4 w0 = *(const float4*)&W2s[kk * 16 + half * 8];
                float4 w1 = *(const float4*)&W2s[kk * 16 + half * 8 + 4];
                sv[0]+=h*w0.x; sv[1]+=h*w0.y; sv[2]+=h*w0.z; sv[3]+=h*w0.w;
                sv[4]+=h*w1.x; sv[5]+=h*w1.y; sv[6]+=h*w1.z; sv[7]+=h*w1.w;
            }
            float sq = 0.f;
            #pragma unroll
            for (int j = 0; j < 8; ++j) { sv[j] = tanhf(sv[j]); sq += sv[j] * sv[j]; }
            sq += __shfl_xor_sync(0xffffffffu, sq, 1);
            *(float4*)&Vs[row * 16 + half * 8]     = make_float4(sv[0], sv[1], sv[2], sv[3]);
            *(float4*)&Vs[row * 16 + half * 8 + 4] = make_float4(sv[4], sv[5], sv[6], sv[7]);
            if (half == 0) SSQ[row] = sq;
        }
        asm volatile("bar.sync 1, 256;" ::: "memory");

        if (t < 64) {
            float d = 0.f;
            #pragma unroll
            for (int j4 = 0; j4 < 4; ++j4) {
                float4 a = *(const float4*)&Vs[t * 16 + j4 * 4];
                float4 b = *(const float4*)&Vs[(t + 64) * 16 + j4 * 4];
                d += a.x * b.x + a.y * b.y + a.z * b.z + a.w * b.w;
            }
            float fid = (d * d) / (SSQ[t] * SSQ[t + 64]);
            out[p0 + t] = fminf(fmaxf(fid, 0.f), 1.f);
        }
    }
}

extern "C" void kernel_launch(void* const* d_in, const int* in_sizes, int n_in,
                              void* d_out, int out_size)
{
    const float* img_a = (const float*)d_in[0];
    const float* img_b = (const float*)d_in[1];
    const float* W1    = (const float*)d_in[2];
    const float* b1    = (const float*)d_in[3];
    const float* W2    = (const float*)d_in[4];
    const float* b2    = (const float*)d_in[5];
    // d_in[6] = theta: unused — the circuit is unitary, fidelity is invariant.
    float* out = (float*)d_out;

    cudaFuncSetAttribute(qcm_ws, cudaFuncAttributeMaxDynamicSharedMemorySize, SMEM_BYTES);
    prep_w1<<<49, 256>>>(W1);                   // W1 -> K-major bf16 hi/lo
    int blocks = out_size / 64;                 // 1024
    qcm_ws<<<blocks, 320, SMEM_BYTES>>>(img_a, img_b, b1, W2, b2, out);
}

// round 12
// speedup vs baseline: 1.2597x; 1.2563x over previous
#include <cuda_runtime.h>
#include <cuda_bf16.h>
#include <cstdint>

// fid[p] = clip( (va.vb)^2 / (|va|^2 |vb|^2), 0, 1 )
// va = tanh( relu(xa @ W1 + b1) @ W2 + b2 )   (quantum circuit is unitary -> cancels)
// R4 skeleton (M=128/block, 8 warps, 32x32 tiles, 1024 blocks, 174.6us) with ONE change:
// B tiles are prepass-converted into byte-exact smem tile images (hi+lo, 6144 B/chunk)
// and staged with fully-coalesced contiguous cp.async. A path identical to R4.

#define KDIM   784
#define KC     16
#define NCHUNK 49
#define ASTR   24      // uint16 elems per smem row (48 B): conflict-free frags + staging
#define HSTR   66
#define BTILE  6144    // per-chunk B image: 3072 B hi + 3072 B lo (64 rows x 48 B each)

__device__ __align__(16) uint8_t g_W1B[NCHUNK * BTILE];   // chunk-image layout

#define MMA(d, a, b) asm volatile( \
    "mma.sync.aligned.m16n8k16.row.col.f32.bf16.bf16.f32 " \
    "{%0,%1,%2,%3}, {%4,%5,%6,%7}, {%8,%9}, {%0,%1,%2,%3};" \
    : "+f"(d[0]), "+f"(d[1]), "+f"(d[2]), "+f"(d[3]) \
    : "r"(a[0]), "r"(a[1]), "r"(a[2]), "r"(a[3]), "r"(b[0]), "r"(b[1]))

__device__ __forceinline__ uint32_t bf2u(__nv_bfloat162 v) { return *(uint32_t*)&v; }

__device__ __forceinline__ uint32_t hi2(float x, float y, uint32_t& lo) {
    __nv_bfloat162 h = __float22bfloat162_rn(make_float2(x, y));
    __nv_bfloat162 l = __float22bfloat162_rn(make_float2(
        x - __bfloat162float(h.x), y - __bfloat162float(h.y)));
    lo = bf2u(l);
    return bf2u(h);
}

// convert float4 -> 4x(hi,lo) bf16, store 8B hi + 8B lo
__device__ __forceinline__ void cvst4(float4 v, uint16_t* hi, uint16_t* lo) {
    uint2 h, l;
    h.x = hi2(v.x, v.y, l.x);
    h.y = hi2(v.z, v.w, l.y);
    *(uint2*)hi = h;
    *(uint2*)lo = l;
}

__device__ __forceinline__ void cp16(uint32_t dst, const void* src) {
    asm volatile("cp.async.ca.shared.global [%0], [%1], 16;" :: "r"(dst), "l"(src));
}

// Build per-chunk B tile images: block c handles chunk c.
// Row n of the tile: 16 k-values as bf16 at bytes [0,32) of a 48-B row; hi tile then lo tile.
__global__ void prep_w1(const float* __restrict__ W1) {
    int c = blockIdx.x;                 // 0..48
    int r = threadIdx.x;                // 0..255
    int n = r >> 2;                     // 0..63 col
    int q = r & 3;                      // 0..3 k-quad
    int k = c * 16 + q * 4;
    float v0 = W1[(size_t)(k + 0) * 64 + n];
    float v1 = W1[(size_t)(k + 1) * 64 + n];
    float v2 = W1[(size_t)(k + 2) * 64 + n];
    float v3 = W1[(size_t)(k + 3) * 64 + n];
    uint32_t l0, l1;
    uint32_t h0 = hi2(v0, v1, l0);
    uint32_t h1 = hi2(v2, v3, l1);
    uint8_t* dst = g_W1B + (size_t)c * BTILE + n * 48 + q * 8;
    *(uint2*)dst          = make_uint2(h0, h1);
    *(uint2*)(dst + 3072) = make_uint2(l0, l1);
}

__global__ __launch_bounds__(256, 3)
void qcm_mma(const float* __restrict__ img_a,
             const float* __restrict__ img_b,
             const float* __restrict__ b1,
             const float* __restrict__ W2,
             const float* __restrict__ b2,
             float* __restrict__ out)
{
    __shared__ __align__(16) union {
        struct {
            uint16_t Ahi[2][128 * ASTR];   // 2 x 6144 B
            uint16_t Alo[2][128 * ASTR];
            uint8_t  Bs[2][BTILE];         // 2 x (3072 hi + 3072 lo)
        } m;                               // 36864 B
        struct {
            float H[128 * HSTR];
            float Vs[128 * 16];
            float ssq[128];
        } e;
    } sm;
    __shared__ float W2s[64 * 16];
    __shared__ float b1s[64];
    __shared__ float b2s[16];

    const int t    = threadIdx.x;
    const int lane = t & 31;
    const int wid  = t >> 5;
    const int wr   = wid >> 1;        // 0..3 : 32-row band
    const int wc   = wid & 1;         // 0..1 : 32-col half
    const int g    = lane >> 2;
    const int tig  = lane & 3;
    const int p0   = blockIdx.x * 64; // 64 pairs per block (128 rows)

    // params
    if (t < 64) b1s[t] = b1[t];
    if (t < 16) b2s[t] = b2[t];
    #pragma unroll
    for (int i = 0; i < 4; ++i) W2s[t + i * 256] = W2[t + i * 256];

    // A staging: thread t owns row (t>>1), k-halves of the 16-chunk (identical to R4)
    const int arow = t >> 1;
    const int ak   = (t & 1) * 8;
    const float* abase = (arow < 64 ? img_a + (size_t)(p0 + arow) * KDIM
                                    : img_b + (size_t)(p0 + arow - 64) * KDIM);

    // B staging: contiguous 6144-B chunk image, 384 x 16B tasks over 256 threads
    const uint32_t sbB0 = (uint32_t)__cvta_generic_to_shared(sm.m.Bs[0]);
    const uint32_t sbB1 = (uint32_t)__cvta_generic_to_shared(sm.m.Bs[1]);

    float acc[2][4][4];
    #pragma unroll
    for (int mt = 0; mt < 2; ++mt)
        #pragma unroll
        for (int nt = 0; nt < 4; ++nt)
            #pragma unroll
            for (int j = 0; j < 4; ++j) acc[mt][nt][j] = 0.f;

    // ---- prologue: stage chunk 0 ----
    {
        const uint8_t* src = g_W1B;
        cp16(sbB0 + t * 16, src + t * 16);
        if (t < 128) cp16(sbB0 + 4096 + t * 16, src + 4096 + t * 16);
        asm volatile("cp.async.commit_group;" ::: "memory");
        float4 v0 = *(const float4*)(abase + ak);
        float4 v1 = *(const float4*)(abase + ak + 4);
        cvst4(v0, &sm.m.Ahi[0][arow * ASTR + ak],     &sm.m.Alo[0][arow * ASTR + ak]);
        cvst4(v1, &sm.m.Ahi[0][arow * ASTR + ak + 4], &sm.m.Alo[0][arow * ASTR + ak + 4]);
        asm volatile("cp.async.wait_group 0;" ::: "memory");
    }
    __syncthreads();

    // ---- mainloop ----
    for (int c = 0; c < NCHUNK; ++c) {
        const int st = c & 1;
        const int nb = st ^ 1;
        const bool more = (c + 1 < NCHUNK);

        float4 va0, va1;
        if (more) {
            const int k1 = (c + 1) * KC;
            const uint8_t* src = g_W1B + (size_t)(c + 1) * BTILE;
            const uint32_t dstb = nb ? sbB1 : sbB0;
            cp16(dstb + t * 16, src + t * 16);
            if (t < 128) cp16(dstb + 4096 + t * 16, src + 4096 + t * 16);
            asm volatile("cp.async.commit_group;" ::: "memory");
            va0 = *(const float4*)(abase + k1 + ak);
            va1 = *(const float4*)(abase + k1 + ak + 4);
        }

        const uint16_t* Ah = sm.m.Ahi[st];
        const uint16_t* Al = sm.m.Alo[st];
        const uint16_t* Bh = (const uint16_t*)(sm.m.Bs[st]);
        const uint16_t* Bl = (const uint16_t*)(sm.m.Bs[st] + 3072);

        uint32_t bh[4][2], bl[4][2];
        #pragma unroll
        for (int nt = 0; nt < 4; ++nt) {
            int bb = (wc * 32 + nt * 8 + g) * ASTR + 2 * tig;
            bh[nt][0] = *(const uint32_t*)&Bh[bb];
            bh[nt][1] = *(const uint32_t*)&Bh[bb + 8];
            bl[nt][0] = *(const uint32_t*)&Bl[bb];
            bl[nt][1] = *(const uint32_t*)&Bl[bb + 8];
        }

        #pragma unroll
        for (int mt = 0; mt < 2; ++mt) {
            int r0 = (wr * 32 + mt * 16 + g) * ASTR + 2 * tig;
            uint32_t ah[4], al[4];
            ah[0] = *(const uint32_t*)&Ah[r0];
            ah[1] = *(const uint32_t*)&Ah[r0 + 8 * ASTR];
            ah[2] = *(const uint32_t*)&Ah[r0 + 8];
            ah[3] = *(const uint32_t*)&Ah[r0 + 8 * ASTR + 8];
            al[0] = *(const uint32_t*)&Al[r0];
            al[1] = *(const uint32_t*)&Al[r0 + 8 * ASTR];
            al[2] = *(const uint32_t*)&Al[r0 + 8];
            al[3] = *(const uint32_t*)&Al[r0 + 8 * ASTR + 8];
            #pragma unroll
            for (int nt = 0; nt < 4; ++nt) {
                MMA(acc[mt][nt], ah, bh[nt]);
                MMA(acc[mt][nt], ah, bl[nt]);
                MMA(acc[mt][nt], al, bh[nt]);
            }
        }

        if (more) {
            cvst4(va0, &sm.m.Ahi[nb][arow * ASTR + ak],     &sm.m.Alo[nb][arow * ASTR + ak]);
            cvst4(va1, &sm.m.Ahi[nb][arow * ASTR + ak + 4], &sm.m.Alo[nb][arow * ASTR + ak + 4]);
        }
        asm volatile("cp.async.wait_group 0;" ::: "memory");
        __syncthreads();
    }

    // ---- epilogue: H = relu(acc + b1) into smem (fragment layout scatter) ----
    #pragma unroll
    for (int mt = 0; mt < 2; ++mt) {
        #pragma unroll
        for (int nt = 0; nt < 4; ++nt) {
            int row = wr * 32 + mt * 16 + g;
            int col = wc * 32 + nt * 8 + 2 * tig;
            float bx = b1s[col], by = b1s[col + 1];
            *(float2*)&sm.e.H[row * HSTR + col] =
                make_float2(fmaxf(acc[mt][nt][0] + bx, 0.f), fmaxf(acc[mt][nt][1] + by, 0.f));
            *(float2*)&sm.e.H[(row + 8) * HSTR + col] =
                make_float2(fmaxf(acc[mt][nt][2] + bx, 0.f), fmaxf(acc[mt][nt][3] + by, 0.f));
        }
    }
    __syncthreads();

    // ---- v = tanh(H @ W2 + b2): 2 threads per row, 8 outs each ----
    {
        int row  = t >> 1;
        int half = t & 1;
        float s[8];
        float4 bb0 = *(const float4*)&b2s[half * 8];
        float4 bb1 = *(const float4*)&b2s[half * 8 + 4];
        s[0]=bb0.x; s[1]=bb0.y; s[2]=bb0.z; s[3]=bb0.w;
        s[4]=bb1.x; s[5]=bb1.y; s[6]=bb1.z; s[7]=bb1.w;
        #pragma unroll 8
        for (int kk = 0; kk < 64; ++kk) {
            float h = sm.e.H[row * HSTR + kk];
            float4 w0 = *(const float4*)&W2s[kk * 16 + half * 8];
            float4 w1 = *(const float4*)&W2s[kk * 16 + half * 8 + 4];
            s[0]+=h*w0.x; s[1]+=h*w0.y; s[2]+=h*w0.z; s[3]+=h*w0.w;
            s[4]+=h*w1.x; s[5]+=h*w1.y; s[6]+=h*w1.z; s[7]+=h*w1.w;
        }
        float sq = 0.f;
        #pragma unroll
        for (int j = 0; j < 8; ++j) { s[j] = tanhf(s[j]); sq += s[j] * s[j]; }
        sq += __shfl_xor_sync(0xffffffffu, sq, 1);
        *(float4*)&sm.e.Vs[row * 16 + half * 8]     = make_float4(s[0], s[1], s[2], s[3]);
        *(float4*)&sm.e.Vs[row * 16 + half * 8 + 4] = make_float4(s[4], s[5], s[6], s[7]);
        if (half == 0) sm.e.ssq[row] = sq;
    }
    __syncthreads();

    // ---- fid = (va.vb)^2 / (|va|^2 |vb|^2), clipped ----
    if (t < 64) {
        float d = 0.f;
        #pragma unroll
        for (int j4 = 0; j4 < 4; ++j4) {
            float4 a = *(const float4*)&sm.e.Vs[t * 16 + j4 * 4];
            float4 b = *(const float4*)&sm.e.Vs[(t + 64) * 16 + j4 * 4];
            d += a.x * b.x + a.y * b.y + a.z * b.z + a.w * b.w;
        }
        float fid = (d * d) / (sm.e.ssq[t] * sm.e.ssq[t + 64]);
        out[p0 + t] = fminf(fmaxf(fid, 0.f), 1.f);
    }
}

extern "C" void kernel_launch(void* const* d_in, const int* in_sizes, int n_in,
                              void* d_out, int out_size)
{
    const float* img_a = (const float*)d_in[0];
    const float* img_b = (const float*)d_in[1];
    const float* W1    = (const float*)d_in[2];
    const float* b1    = (const float*)d_in[3];
    const float* W2    = (const float*)d_in[4];
    const float* b2    = (const float*)d_in[5];
    // d_in[6] = theta: unused — the circuit is unitary, fidelity is invariant.
    float* out = (float*)d_out;

    prep_w1<<<NCHUNK, 256>>>(W1);               // W1 -> per-chunk bf16 hi/lo tile images
    int blocks = out_size / 64;                 // 1024
    qcm_mma<<<blocks, 256>>>(img_a, img_b, b1, W2, b2, out);
}